// round 3
// baseline (speedup 1.0000x reference)
#include <cuda_runtime.h>
#include <cuda_bf16.h>

#define N_NODES 50000
#define E_EDGES 800000
#define IN_C    16
#define HDIM    64
#define HH      32
#define NLAYERS 3
#define NB      256      // nodes per block in lane-per-node kernels

typedef unsigned long long u64;

// Scratch (device globals)
__device__ float  g_h[HDIM * N_NODES];   // COLUMN-major: g_h[j*N + n]
__device__ float4 g_p4[N_NODES * 8];     // row-major [n][32] (edge kernel gathers rows)
__device__ float4 g_q4[N_NODES * 8];     // row-major [n][32] (edge kernel scatters rows)
__device__ float  g_cnt[N_NODES];

// ---- f32x2 packed helpers (FFMA2 is PTX-only on sm_103a) ----
__device__ __forceinline__ u64 pack2(float lo, float hi) {
    u64 r;
    asm("mov.b64 %0, {%1, %2};" : "=l"(r) : "r"(__float_as_uint(lo)), "r"(__float_as_uint(hi)));
    return r;
}
__device__ __forceinline__ void unpack2(u64 v, float& lo, float& hi) {
    unsigned a, b;
    asm("mov.b64 {%0, %1}, %2;" : "=r"(a), "=r"(b) : "l"(v));
    lo = __uint_as_float(a); hi = __uint_as_float(b);
}
__device__ __forceinline__ u64 fma2(u64 a, u64 b, u64 c) {
    u64 d;
    asm("fma.rn.f32x2 %0, %1, %2, %3;" : "=l"(d) : "l"(a), "l"(b), "l"(c));
    return d;
}
__device__ __forceinline__ void red_add_v4(float* ptr, float4 v) {
    asm volatile("red.global.add.v4.f32 [%0], {%1,%2,%3,%4};"
                 :: "l"(ptr), "f"(v.x), "f"(v.y), "f"(v.z), "f"(v.w) : "memory");
}

// ---------------- degree count ----------------
__global__ void count_kernel(const int* __restrict__ ei) {
    int e = blockIdx.x * blockDim.x + threadIdx.x;
    if (e < E_EDGES) atomicAdd(&g_cnt[ei[E_EDGES + e]], 1.0f);
}

// ---------------- encoder: lane-per-node; also p0 = h@W1a+b1, zero q/cnt ----------------
__global__ __launch_bounds__(256) void encoder_kernel(
    const float* __restrict__ x,  const float* __restrict__ w,
    const float* __restrict__ b,  const float* __restrict__ g,
    const float* __restrict__ beta,
    const float* __restrict__ w1, const float* __restrict__ b1)
{
    __shared__ float sbuf[NB * 33];           // x staging (stride 17) then p staging (stride 33)
    int n0 = blockIdx.x * NB, t = threadIdx.x, n = n0 + t;
    int rem = N_NODES - n0; if (rem > NB) rem = NB;
    bool act = (t < rem);

    // stage x tile coalesced -> padded smem
    {
        const float4* src = (const float4*)(x + (size_t)n0 * IN_C);
        int nf4 = rem * (IN_C / 4);
        for (int i = t; i < nf4; i += NB) {
            float4 v = src[i];
            int f = i * 4, nl = f / IN_C, k = f % IN_C;
            float* d = &sbuf[nl * 17 + k];
            d[0] = v.x; d[1] = v.y; d[2] = v.z; d[3] = v.w;
        }
    }
    // zero q and cnt for this block's nodes
    {
        float4 z = make_float4(0.f, 0.f, 0.f, 0.f);
        for (int i = t; i < rem * 8; i += NB) g_q4[(size_t)n0 * 8 + i] = z;
        if (act) g_cnt[n] = 0.f;
    }
    __syncthreads();

    // GEMV: a = x @ enc_w + enc_b  (64 outputs, f32x2 packed)
    u64 acc[32];
    const u64* bb = (const u64*)b;
#pragma unroll
    for (int j = 0; j < 32; j++) acc[j] = __ldg(&bb[j]);
#pragma unroll
    for (int k = 0; k < IN_C; k++) {
        float xk = sbuf[t * 17 + k];
        u64 xx = pack2(xk, xk);
        const u64* wr = (const u64*)(w + k * HDIM);
#pragma unroll
        for (int j = 0; j < 32; j++) acc[j] = fma2(xx, __ldg(&wr[j]), acc[j]);
    }
    float a[64];
#pragma unroll
    for (int j = 0; j < 32; j++) unpack2(acc[j], a[2 * j], a[2 * j + 1]);

    // LayerNorm + relu (thread-local)
    float s1a = 0.f, s1b = 0.f, s2a = 0.f, s2b = 0.f;
#pragma unroll
    for (int j = 0; j < 64; j += 2) {
        s1a += a[j];     s2a = fmaf(a[j], a[j], s2a);
        s1b += a[j + 1]; s2b = fmaf(a[j + 1], a[j + 1], s2b);
    }
    float mu = (s1a + s1b) * (1.f / 64.f);
    float var = (s2a + s2b) * (1.f / 64.f) - mu * mu;
    float rs = rsqrtf(var + 1e-5f);
#pragma unroll
    for (int j = 0; j < 64; j++) {
        a[j] = fmaxf(fmaf((a[j] - mu) * rs, __ldg(&g[j]), __ldg(&beta[j])), 0.f);
        if (act) g_h[(size_t)j * N_NODES + n] = a[j];
    }

    // p0 = h @ W1[:64] + b1 (32 outputs)
    u64 pacc[16];
    const u64* b1p = (const u64*)b1;
#pragma unroll
    for (int j = 0; j < 16; j++) pacc[j] = __ldg(&b1p[j]);
#pragma unroll
    for (int k = 0; k < 64; k++) {
        u64 hh = pack2(a[k], a[k]);
        const u64* wr = (const u64*)(w1 + k * HH);
#pragma unroll
        for (int j = 0; j < 16; j++) pacc[j] = fma2(hh, __ldg(&wr[j]), pacc[j]);
    }
    __syncthreads();   // done reading x staging
#pragma unroll
    for (int j = 0; j < 16; j++) {
        float lo, hi; unpack2(pacc[j], lo, hi);
        sbuf[t * 33 + 2 * j] = lo; sbuf[t * 33 + 2 * j + 1] = hi;
    }
    __syncthreads();
    {   // coalesced write-out of p (row-major)
        float4* dst = (float4*)g_p4 + (size_t)n0 * 8;
        int nf4 = rem * 8;
        for (int i = t; i < nf4; i += NB) {
            int f = i * 4, nl = f / 32, k = f % 32;
            const float* s = &sbuf[nl * 33 + k];
            dst[i] = make_float4(s[0], s[1], s[2], s[3]);
        }
    }
}

// ---------------- edge kernel (unchanged: at L2 roofline) ----------------
__global__ __launch_bounds__(256) void edge_kernel(
    const int* __restrict__ ei, const float* __restrict__ ea,
    const float* __restrict__ w1)
{
    int idx = blockIdx.x * blockDim.x + threadIdx.x;
    int e = idx >> 3, quad = idx & 7;
    if (e >= E_EDGES) return;

    int src = __ldg(&ei[e]);
    int dst = __ldg(&ei[E_EDGES + e]);
    float e0 = __ldg(&ea[e * 3 + 0]);
    float e1 = __ldg(&ea[e * 3 + 1]);
    float e2 = __ldg(&ea[e * 3 + 2]);

    float4 p = __ldg(&g_p4[src * 8 + quad]);
    const float4* W = (const float4*)(w1 + 64 * HH);
    float4 wa = __ldg(&W[quad]);
    float4 wb = __ldg(&W[8 + quad]);
    float4 wc = __ldg(&W[16 + quad]);

    float4 v;
    v.x = fmaxf(fmaf(e2, wc.x, fmaf(e1, wb.x, fmaf(e0, wa.x, p.x))), 0.0f);
    v.y = fmaxf(fmaf(e2, wc.y, fmaf(e1, wb.y, fmaf(e0, wa.y, p.y))), 0.0f);
    v.z = fmaxf(fmaf(e2, wc.z, fmaf(e1, wb.z, fmaf(e0, wa.z, p.z))), 0.0f);
    v.w = fmaxf(fmaf(e2, wc.w, fmaf(e1, wb.w, fmaf(e0, wa.w, p.w))), 0.0f);

    red_add_v4((float*)&g_q4[dst * 8 + quad], v);
}

// ---- stage-2 + mean + residual + LN (+ fused next-layer p); lane-per-node ----
__global__ __launch_bounds__(256) void node_agg_kernel(
    const float* __restrict__ w2,  const float* __restrict__ b2,
    const float* __restrict__ g,   const float* __restrict__ beta,
    const float* __restrict__ w1n, const float* __restrict__ b1n)
{
    __shared__ float sbuf[NB * 33];   // q staging, then p staging
    int n0 = blockIdx.x * NB, t = threadIdx.x, n = n0 + t;
    int rem = N_NODES - n0; if (rem > NB) rem = NB;
    bool act = (t < rem);

    // stage q coalesced -> padded smem; zero q behind us
    {
        float4* qp = (float4*)g_q4 + (size_t)n0 * 8;
        float4 z = make_float4(0.f, 0.f, 0.f, 0.f);
        int nf4 = rem * 8;
        for (int i = t; i < nf4; i += NB) {
            float4 v = qp[i];
            int f = i * 4, nl = f / 32, k = f % 32;
            float* d = &sbuf[nl * 33 + k];
            d[0] = v.x; d[1] = v.y; d[2] = v.z; d[3] = v.w;
            qp[i] = z;
        }
    }
    __syncthreads();

    // stage-2 GEMV: o = q @ W2 (64 outputs)
    u64 acc[32];
#pragma unroll
    for (int j = 0; j < 32; j++) acc[j] = 0ull;
#pragma unroll
    for (int k = 0; k < 32; k++) {
        float qk = sbuf[t * 33 + k];
        u64 qq = pack2(qk, qk);
        const u64* wr = (const u64*)(w2 + k * HDIM);
#pragma unroll
        for (int j = 0; j < 32; j++) acc[j] = fma2(qq, __ldg(&wr[j]), acc[j]);
    }
    float c = act ? g_cnt[n] : 0.f;
    float inv = (c > 0.f) ? (1.f / c) : 0.f;
    float has = (c > 0.f) ? 1.f : 0.f;

    float a[64];
#pragma unroll
    for (int j = 0; j < 32; j++) {
        float lo, hi; unpack2(acc[j], lo, hi);
        int j0 = 2 * j, j1 = 2 * j + 1;
        float h0 = act ? g_h[(size_t)j0 * N_NODES + n] : 0.f;
        float h1 = act ? g_h[(size_t)j1 * N_NODES + n] : 0.f;
        a[j0] = h0 + lo * inv + has * __ldg(&b2[j0]);
        a[j1] = h1 + hi * inv + has * __ldg(&b2[j1]);
    }
    // LayerNorm (thread-local)
    float s1a = 0.f, s1b = 0.f, s2a = 0.f, s2b = 0.f;
#pragma unroll
    for (int j = 0; j < 64; j += 2) {
        s1a += a[j];     s2a = fmaf(a[j], a[j], s2a);
        s1b += a[j + 1]; s2b = fmaf(a[j + 1], a[j + 1], s2b);
    }
    float mu = (s1a + s1b) * (1.f / 64.f);
    float var = (s2a + s2b) * (1.f / 64.f) - mu * mu;
    float rs = rsqrtf(var + 1e-5f);
#pragma unroll
    for (int j = 0; j < 64; j++) {
        a[j] = fmaf((a[j] - mu) * rs, __ldg(&g[j]), __ldg(&beta[j]));
        if (act) g_h[(size_t)j * N_NODES + n] = a[j];
    }

    if (w1n != nullptr) {   // fused p for next layer
        u64 pacc[16];
        const u64* b1p = (const u64*)b1n;
#pragma unroll
        for (int j = 0; j < 16; j++) pacc[j] = __ldg(&b1p[j]);
#pragma unroll
        for (int k = 0; k < 64; k++) {
            u64 hh = pack2(a[k], a[k]);
            const u64* wr = (const u64*)(w1n + k * HH);
#pragma unroll
            for (int j = 0; j < 16; j++) pacc[j] = fma2(hh, __ldg(&wr[j]), pacc[j]);
        }
        __syncthreads();
#pragma unroll
        for (int j = 0; j < 16; j++) {
            float lo, hi; unpack2(pacc[j], lo, hi);
            sbuf[t * 33 + 2 * j] = lo; sbuf[t * 33 + 2 * j + 1] = hi;
        }
        __syncthreads();
        float4* dst = (float4*)g_p4 + (size_t)n0 * 8;
        int nf4 = rem * 8;
        for (int i = t; i < nf4; i += NB) {
            int f = i * 4, nl = f / 32, k = f % 32;
            const float* s = &sbuf[nl * 33 + k];
            dst[i] = make_float4(s[0], s[1], s[2], s[3]);
        }
    }
}

// ---------------- heads (lane-per-node, two passes to limit regs) ----------------
__global__ __launch_bounds__(256) void heads_kernel(
    const float* __restrict__ dw1, const float* __restrict__ db1,
    const float* __restrict__ dw2, const float* __restrict__ db2,
    const float* __restrict__ vw1, const float* __restrict__ vb1,
    const float* __restrict__ vw2, const float* __restrict__ vb2,
    float* __restrict__ out)
{
    int n0 = blockIdx.x * NB, t = threadIdx.x, n = n0 + t;
    int rem = N_NODES - n0; if (rem > NB) rem = NB;
    bool act = (t < rem);

    float h[64];
#pragma unroll
    for (int j = 0; j < 64; j++)
        h[j] = act ? g_h[(size_t)j * N_NODES + n] : 0.f;

    // depth head
    u64 dacc[16];
    const u64* dbp = (const u64*)db1;
#pragma unroll
    for (int j = 0; j < 16; j++) dacc[j] = __ldg(&dbp[j]);
#pragma unroll
    for (int k = 0; k < 64; k++) {
        u64 hh = pack2(h[k], h[k]);
        const u64* wr = (const u64*)(dw1 + k * HH);
#pragma unroll
        for (int j = 0; j < 16; j++) dacc[j] = fma2(hh, __ldg(&wr[j]), dacc[j]);
    }
    float d = 0.f;
#pragma unroll
    for (int j = 0; j < 16; j++) {
        float lo, hi; unpack2(dacc[j], lo, hi);
        lo = fmaxf(lo, 0.f); hi = fmaxf(hi, 0.f);
        d = fmaf(lo, __ldg(&dw2[2 * j]), fmaf(hi, __ldg(&dw2[2 * j + 1]), d));
    }

    // velocity head
    u64 vacc[16];
    const u64* vbp = (const u64*)vb1;
#pragma unroll
    for (int j = 0; j < 16; j++) vacc[j] = __ldg(&vbp[j]);
#pragma unroll
    for (int k = 0; k < 64; k++) {
        u64 hh = pack2(h[k], h[k]);
        const u64* wr = (const u64*)(vw1 + k * HH);
#pragma unroll
        for (int j = 0; j < 16; j++) vacc[j] = fma2(hh, __ldg(&wr[j]), vacc[j]);
    }
    float v0 = 0.f, v1 = 0.f;
#pragma unroll
    for (int j = 0; j < 16; j++) {
        float lo, hi; unpack2(vacc[j], lo, hi);
        lo = fmaxf(lo, 0.f); hi = fmaxf(hi, 0.f);
        v0 = fmaf(lo, __ldg(&vw2[4 * j + 0]), fmaf(hi, __ldg(&vw2[4 * j + 2]), v0));
        v1 = fmaf(lo, __ldg(&vw2[4 * j + 1]), fmaf(hi, __ldg(&vw2[4 * j + 3]), v1));
    }

    if (act) {
        out[n] = d + __ldg(&db2[0]);
        float2* vout = (float2*)(out + N_NODES);
        vout[n] = make_float2(v0 + __ldg(&vb2[0]), v1 + __ldg(&vb2[1]));
    }
}

// ---------------- launch ----------------
extern "C" void kernel_launch(void* const* d_in, const int* in_sizes, int n_in,
                              void* d_out, int out_size)
{
    const float* x       = (const float*)d_in[0];
    const int*   ei      = (const int*)  d_in[1];
    const float* ea      = (const float*)d_in[2];
    const float* enc_w   = (const float*)d_in[3];
    const float* enc_b   = (const float*)d_in[4];
    const float* enc_g   = (const float*)d_in[5];
    const float* enc_bt  = (const float*)d_in[6];
    const float* mlp_w1  = (const float*)d_in[7];   // [L, 67, 32]
    const float* mlp_b1  = (const float*)d_in[8];   // [L, 32]
    const float* mlp_w2  = (const float*)d_in[9];   // [L, 32, 64]
    const float* mlp_b2  = (const float*)d_in[10];  // [L, 64]
    const float* ln_g    = (const float*)d_in[11];  // [L, 64]
    const float* ln_b    = (const float*)d_in[12];  // [L, 64]
    const float* dw1     = (const float*)d_in[13];
    const float* db1     = (const float*)d_in[14];
    const float* dw2     = (const float*)d_in[15];
    const float* db2     = (const float*)d_in[16];
    const float* vw1     = (const float*)d_in[17];
    const float* vb1     = (const float*)d_in[18];
    const float* vw2     = (const float*)d_in[19];
    const float* vb2     = (const float*)d_in[20];
    float* out = (float*)d_out;

    const int TB = 256;
    const int node_grid = (N_NODES + NB - 1) / NB;       // lane-per-node
    const int edge_grid = (E_EDGES * 8 + TB - 1) / TB;   // 8 threads/edge

    encoder_kernel<<<node_grid, TB>>>(x, enc_w, enc_b, enc_g, enc_bt,
                                      mlp_w1, mlp_b1);
    count_kernel<<<(E_EDGES + TB - 1) / TB, TB>>>(ei);

    for (int i = 0; i < NLAYERS; i++) {
        const float* w1 = mlp_w1 + (size_t)i * (HDIM + 3) * HH;
        const float* w2 = mlp_w2 + (size_t)i * HH * HDIM;
        const float* b2 = mlp_b2 + (size_t)i * HDIM;
        const float* lg = ln_g   + (size_t)i * HDIM;
        const float* lb = ln_b   + (size_t)i * HDIM;
        const float* w1n = (i + 1 < NLAYERS) ? mlp_w1 + (size_t)(i + 1) * (HDIM + 3) * HH : nullptr;
        const float* b1n = (i + 1 < NLAYERS) ? mlp_b1 + (size_t)(i + 1) * HH : nullptr;

        edge_kernel<<<edge_grid, TB>>>(ei, ea, w1);
        node_agg_kernel<<<node_grid, TB>>>(w2, b2, lg, lb, w1n, b1n);
    }

    heads_kernel<<<node_grid, TB>>>(dw1, db1, dw2, db2, vw1, vb1, vw2, vb2, out);
}

// round 4
// speedup vs baseline: 1.6420x; 1.6420x over previous
#include <cuda_runtime.h>
#include <cuda_bf16.h>

#define N_NODES 50000
#define E_EDGES 800000
#define IN_C    16
#define HDIM    64
#define HH      32
#define NLAYERS 3
#define FULL    0xffffffffu

// Scratch (device globals; float4 for 16B alignment)
__device__ float  g_h[N_NODES * HDIM];   // row-major [n][64], lane j holds (j, j+32)
__device__ float4 g_p4[N_NODES * 8];     // row-major [n][32]
__device__ float4 g_q4[N_NODES * 8];     // row-major [n][32]
__device__ float  g_cnt[N_NODES];

__device__ __forceinline__ void red_add_v4(float* ptr, float4 v) {
    asm volatile("red.global.add.v4.f32 [%0], {%1,%2,%3,%4};"
                 :: "l"(ptr), "f"(v.x), "f"(v.y), "f"(v.z), "f"(v.w) : "memory");
}

// ---------------- encoder (R2, proven): h + p0 + zero q/cnt ----------------
__global__ __launch_bounds__(256) void encoder_kernel(
    const float* __restrict__ x,  const float* __restrict__ w,
    const float* __restrict__ b,  const float* __restrict__ g,
    const float* __restrict__ beta,
    const float* __restrict__ w1, const float* __restrict__ b1)
{
    int warp = (blockIdx.x * blockDim.x + threadIdx.x) >> 5;
    int lane = threadIdx.x & 31;
    int n0   = warp * 4;
    if (n0 >= N_NODES) return;

    float* g_p = (float*)g_p4;
    float* g_q = (float*)g_q4;

    float xv[4], a0[4], a1[4];
#pragma unroll
    for (int i = 0; i < 4; i++) {
        xv[i] = (lane < IN_C) ? x[(n0 + i) * IN_C + lane] : 0.0f;
        a0[i] = __ldg(&b[lane]);
        a1[i] = __ldg(&b[lane + 32]);
    }
#pragma unroll
    for (int k = 0; k < IN_C; k++) {
        float w0 = __ldg(&w[k * HDIM + lane]);
        float w1v = __ldg(&w[k * HDIM + 32 + lane]);
#pragma unroll
        for (int i = 0; i < 4; i++) {
            float xk = __shfl_sync(FULL, xv[i], k);
            a0[i] = fmaf(xk, w0, a0[i]);
            a1[i] = fmaf(xk, w1v, a1[i]);
        }
    }
    float gl = __ldg(&g[lane]), gh = __ldg(&g[lane + 32]);
    float bl = __ldg(&beta[lane]), bh = __ldg(&beta[lane + 32]);
    float h0[4], h1[4];
#pragma unroll
    for (int i = 0; i < 4; i++) {
        float s1 = a0[i] + a1[i], s2 = a0[i] * a0[i] + a1[i] * a1[i];
#pragma unroll
        for (int o = 16; o; o >>= 1) {
            s1 += __shfl_xor_sync(FULL, s1, o);
            s2 += __shfl_xor_sync(FULL, s2, o);
        }
        float mu  = s1 * (1.0f / 64.0f);
        float var = s2 * (1.0f / 64.0f) - mu * mu;
        float rs  = rsqrtf(var + 1e-5f);
        h0[i] = fmaxf(fmaf((a0[i] - mu) * rs, gl, bl), 0.0f);
        h1[i] = fmaxf(fmaf((a1[i] - mu) * rs, gh, bh), 0.0f);
        g_h[(n0 + i) * HDIM + lane]      = h0[i];
        g_h[(n0 + i) * HDIM + 32 + lane] = h1[i];
    }
    float acc[4];
#pragma unroll
    for (int i = 0; i < 4; i++) acc[i] = __ldg(&b1[lane]);
#pragma unroll
    for (int k = 0; k < 32; k++) {
        float wk = __ldg(&w1[k * HH + lane]);
#pragma unroll
        for (int i = 0; i < 4; i++)
            acc[i] = fmaf(__shfl_sync(FULL, h0[i], k), wk, acc[i]);
    }
#pragma unroll
    for (int k = 0; k < 32; k++) {
        float wk = __ldg(&w1[(32 + k) * HH + lane]);
#pragma unroll
        for (int i = 0; i < 4; i++)
            acc[i] = fmaf(__shfl_sync(FULL, h1[i], k), wk, acc[i]);
    }
#pragma unroll
    for (int i = 0; i < 4; i++) {
        g_p[(n0 + i) * HH + lane] = acc[i];
        g_q[(n0 + i) * HH + lane] = 0.0f;
    }
    if (lane < 4) g_cnt[n0 + lane] = 0.0f;
}

// ---------------- edge kernel; COUNT folds in-degree (layer 0) ----------------
template<bool COUNT>
__global__ __launch_bounds__(256) void edge_kernel(
    const int* __restrict__ ei, const float* __restrict__ ea,
    const float* __restrict__ w1)
{
    int idx = blockIdx.x * blockDim.x + threadIdx.x;
    int e = idx >> 3, quad = idx & 7;
    if (e >= E_EDGES) return;

    int src = __ldg(&ei[e]);
    int dst = __ldg(&ei[E_EDGES + e]);
    float e0 = __ldg(&ea[e * 3 + 0]);
    float e1 = __ldg(&ea[e * 3 + 1]);
    float e2 = __ldg(&ea[e * 3 + 2]);

    float4 p = __ldg(&g_p4[src * 8 + quad]);
    const float4* W = (const float4*)(w1 + 64 * HH);
    float4 wa = __ldg(&W[quad]);
    float4 wb = __ldg(&W[8 + quad]);
    float4 wc = __ldg(&W[16 + quad]);

    float4 v;
    v.x = fmaxf(fmaf(e2, wc.x, fmaf(e1, wb.x, fmaf(e0, wa.x, p.x))), 0.0f);
    v.y = fmaxf(fmaf(e2, wc.y, fmaf(e1, wb.y, fmaf(e0, wa.y, p.y))), 0.0f);
    v.z = fmaxf(fmaf(e2, wc.z, fmaf(e1, wb.z, fmaf(e0, wa.z, p.z))), 0.0f);
    v.w = fmaxf(fmaf(e2, wc.w, fmaf(e1, wb.w, fmaf(e0, wa.w, p.w))), 0.0f);

    red_add_v4((float*)&g_q4[dst * 8 + quad], v);
    if (COUNT && quad == 0) atomicAdd(&g_cnt[dst], 1.0f);
}

// ---- stage-2 + mean + residual + LN; transposed-smem broadcast; LAST fuses heads ----
template<bool LAST>
__global__ __launch_bounds__(256) void node_agg_kernel(
    const float* __restrict__ w2,  const float* __restrict__ b2,
    const float* __restrict__ g,   const float* __restrict__ beta,
    const float* __restrict__ w1n, const float* __restrict__ b1n,
    const float* __restrict__ dw1, const float* __restrict__ db1,
    const float* __restrict__ dw2, const float* __restrict__ db2,
    const float* __restrict__ vw1, const float* __restrict__ vb1,
    const float* __restrict__ vw2, const float* __restrict__ vb2,
    float* __restrict__ out)
{
    __shared__ float sbuf[64 * 36];   // [k][node], stride 36; q uses rows 0-31, then h rows 0-63
    int t = threadIdx.x, w = t >> 5, lane = t & 31;
    int n0 = blockIdx.x * 32;
    int rem = N_NODES - n0; if (rem > 32) rem = 32;

    // stage q transposed; zero q behind us
    {
        int nl = t >> 3, k0 = (t & 7) << 2;
        float4 v = make_float4(0.f, 0.f, 0.f, 0.f);
        float4* qp = (float4*)g_q4 + (size_t)n0 * 8 + t;
        if (nl < rem) { v = *qp; *qp = make_float4(0.f, 0.f, 0.f, 0.f); }
        sbuf[(k0 + 0) * 36 + nl] = v.x;
        sbuf[(k0 + 1) * 36 + nl] = v.y;
        sbuf[(k0 + 2) * 36 + nl] = v.z;
        sbuf[(k0 + 3) * 36 + nl] = v.w;
    }
    __syncthreads();

    int nb = w * 4;   // this warp's 4 nodes: n0+nb .. n0+nb+3

    // stage-2 GEMV: o = q @ W2, lane j holds outputs (j, j+32)
    float o0[4] = {0, 0, 0, 0}, o1[4] = {0, 0, 0, 0};
#pragma unroll
    for (int k = 0; k < 32; k++) {
        float4 qv = *(const float4*)&sbuf[k * 36 + nb];
        float wlo = __ldg(&w2[k * HDIM + lane]);
        float whi = __ldg(&w2[k * HDIM + 32 + lane]);
        o0[0] = fmaf(qv.x, wlo, o0[0]); o1[0] = fmaf(qv.x, whi, o1[0]);
        o0[1] = fmaf(qv.y, wlo, o0[1]); o1[1] = fmaf(qv.y, whi, o1[1]);
        o0[2] = fmaf(qv.z, wlo, o0[2]); o1[2] = fmaf(qv.z, whi, o1[2]);
        o0[3] = fmaf(qv.w, wlo, o0[3]); o1[3] = fmaf(qv.w, whi, o1[3]);
    }
    float b2l = __ldg(&b2[lane]),  b2h = __ldg(&b2[32 + lane]);
    float gl  = __ldg(&g[lane]),   gh  = __ldg(&g[lane + 32]);
    float bl  = __ldg(&beta[lane]), bh = __ldg(&beta[lane + 32]);

    float h0[4], h1[4];
#pragma unroll
    for (int i = 0; i < 4; i++) {
        int n = n0 + nb + i;
        bool act = (nb + i) < rem;
        float c   = act ? g_cnt[n] : 0.f;
        float inv = (c > 0.f) ? (1.f / c) : 0.f;
        float has = (c > 0.f) ? 1.f : 0.f;
        float hh0 = act ? g_h[(size_t)n * HDIM + lane] : 0.f;
        float hh1 = act ? g_h[(size_t)n * HDIM + 32 + lane] : 0.f;
        float a0 = hh0 + o0[i] * inv + has * b2l;
        float a1 = hh1 + o1[i] * inv + has * b2h;
        float s1 = a0 + a1, s2 = a0 * a0 + a1 * a1;
#pragma unroll
        for (int o = 16; o; o >>= 1) {
            s1 += __shfl_xor_sync(FULL, s1, o);
            s2 += __shfl_xor_sync(FULL, s2, o);
        }
        float mu  = s1 * (1.f / 64.f);
        float var = s2 * (1.f / 64.f) - mu * mu;
        float rs  = rsqrtf(var + 1e-5f);
        h0[i] = fmaf((a0 - mu) * rs, gl, bl);
        h1[i] = fmaf((a1 - mu) * rs, gh, bh);
        if (!LAST && act) {
            g_h[(size_t)n * HDIM + lane]      = h0[i];
            g_h[(size_t)n * HDIM + 32 + lane] = h1[i];
        }
    }
    __syncthreads();   // all warps done reading q rows before h overwrite

    // stage h_new transposed: sbuf[k][node]
#pragma unroll
    for (int i = 0; i < 4; i++) {
        sbuf[lane * 36 + nb + i]        = h0[i];
        sbuf[(lane + 32) * 36 + nb + i] = h1[i];
    }
    __syncthreads();

    if (!LAST) {
        // p_next = h_new @ W1n[:64] + b1n; lane j holds output j
        float pacc[4];
        float bb = __ldg(&b1n[lane]);
#pragma unroll
        for (int i = 0; i < 4; i++) pacc[i] = bb;
#pragma unroll
        for (int k = 0; k < 64; k++) {
            float4 hv = *(const float4*)&sbuf[k * 36 + nb];
            float wk = __ldg(&w1n[k * HH + lane]);
            pacc[0] = fmaf(hv.x, wk, pacc[0]);
            pacc[1] = fmaf(hv.y, wk, pacc[1]);
            pacc[2] = fmaf(hv.z, wk, pacc[2]);
            pacc[3] = fmaf(hv.w, wk, pacc[3]);
        }
        float* gp = (float*)g_p4;
#pragma unroll
        for (int i = 0; i < 4; i++)
            if ((nb + i) < rem) gp[(size_t)(n0 + nb + i) * HH + lane] = pacc[i];
    } else {
        // heads: lane j holds hidden unit j of each head
        float da[4], va[4];
        float dbi = __ldg(&db1[lane]), vbi = __ldg(&vb1[lane]);
#pragma unroll
        for (int i = 0; i < 4; i++) { da[i] = dbi; va[i] = vbi; }
#pragma unroll
        for (int k = 0; k < 64; k++) {
            float4 hv = *(const float4*)&sbuf[k * 36 + nb];
            float dwk = __ldg(&dw1[k * HH + lane]);
            float vwk = __ldg(&vw1[k * HH + lane]);
            da[0] = fmaf(hv.x, dwk, da[0]); va[0] = fmaf(hv.x, vwk, va[0]);
            da[1] = fmaf(hv.y, dwk, da[1]); va[1] = fmaf(hv.y, vwk, va[1]);
            da[2] = fmaf(hv.z, dwk, da[2]); va[2] = fmaf(hv.z, vwk, va[2]);
            da[3] = fmaf(hv.w, dwk, da[3]); va[3] = fmaf(hv.w, vwk, va[3]);
        }
        float w2d  = __ldg(&dw2[lane]);
        float w2v0 = __ldg(&vw2[lane * 2 + 0]);
        float w2v1 = __ldg(&vw2[lane * 2 + 1]);
#pragma unroll
        for (int i = 0; i < 4; i++) {
            float rd = fmaxf(da[i], 0.f), rv = fmaxf(va[i], 0.f);
            float d  = rd * w2d;
            float v0 = rv * w2v0;
            float v1 = rv * w2v1;
#pragma unroll
            for (int o = 16; o; o >>= 1) {
                d  += __shfl_xor_sync(FULL, d, o);
                v0 += __shfl_xor_sync(FULL, v0, o);
                v1 += __shfl_xor_sync(FULL, v1, o);
            }
            int n = n0 + nb + i;
            if (lane == 0 && (nb + i) < rem) {
                out[n] = d + __ldg(&db2[0]);
                float2* vout = (float2*)(out + N_NODES);
                vout[n] = make_float2(v0 + __ldg(&vb2[0]), v1 + __ldg(&vb2[1]));
            }
        }
    }
}

// ---------------- launch ----------------
extern "C" void kernel_launch(void* const* d_in, const int* in_sizes, int n_in,
                              void* d_out, int out_size)
{
    const float* x       = (const float*)d_in[0];
    const int*   ei      = (const int*)  d_in[1];
    const float* ea      = (const float*)d_in[2];
    const float* enc_w   = (const float*)d_in[3];
    const float* enc_b   = (const float*)d_in[4];
    const float* enc_g   = (const float*)d_in[5];
    const float* enc_bt  = (const float*)d_in[6];
    const float* mlp_w1  = (const float*)d_in[7];   // [L, 67, 32]
    const float* mlp_b1  = (const float*)d_in[8];   // [L, 32]
    const float* mlp_w2  = (const float*)d_in[9];   // [L, 32, 64]
    const float* mlp_b2  = (const float*)d_in[10];  // [L, 64]
    const float* ln_g    = (const float*)d_in[11];  // [L, 64]
    const float* ln_b    = (const float*)d_in[12];  // [L, 64]
    const float* dw1     = (const float*)d_in[13];
    const float* db1     = (const float*)d_in[14];
    const float* dw2     = (const float*)d_in[15];
    const float* db2     = (const float*)d_in[16];
    const float* vw1     = (const float*)d_in[17];
    const float* vb1     = (const float*)d_in[18];
    const float* vw2     = (const float*)d_in[19];
    const float* vb2     = (const float*)d_in[20];
    float* out = (float*)d_out;

    const int TB = 256;
    const int enc_grid  = (N_NODES / 4 * 32 + TB - 1) / TB;   // 4 nodes/warp
    const int node_grid = (N_NODES + 31) / 32;                // 32 nodes/block
    const int edge_grid = (E_EDGES * 8 + TB - 1) / TB;        // 8 threads/edge

    encoder_kernel<<<enc_grid, TB>>>(x, enc_w, enc_b, enc_g, enc_bt,
                                     mlp_w1, mlp_b1);

    for (int i = 0; i < NLAYERS; i++) {
        const float* w1 = mlp_w1 + (size_t)i * (HDIM + 3) * HH;
        const float* w2 = mlp_w2 + (size_t)i * HH * HDIM;
        const float* b2 = mlp_b2 + (size_t)i * HDIM;
        const float* lg = ln_g   + (size_t)i * HDIM;
        const float* lb = ln_b   + (size_t)i * HDIM;
        const float* w1n = mlp_w1 + (size_t)(i + 1) * (HDIM + 3) * HH;
        const float* b1n = mlp_b1 + (size_t)(i + 1) * HH;

        if (i == 0) edge_kernel<true ><<<edge_grid, TB>>>(ei, ea, w1);
        else        edge_kernel<false><<<edge_grid, TB>>>(ei, ea, w1);

        if (i + 1 < NLAYERS)
            node_agg_kernel<false><<<node_grid, TB>>>(w2, b2, lg, lb, w1n, b1n,
                dw1, db1, dw2, db2, vw1, vb1, vw2, vb2, out);
        else
            node_agg_kernel<true ><<<node_grid, TB>>>(w2, b2, lg, lb, nullptr, nullptr,
                dw1, db1, dw2, db2, vw1, vb1, vw2, vb2, out);
    }
}